// round 5
// baseline (speedup 1.0000x reference)
#include <cuda_runtime.h>

// ---------------- problem constants ----------------
#define TOTAL_BINS 28749
#define BATCH      2048
#define ROWS       4096      // BATCH * 2 channels
#define INPUT_DIM  2200      // 22 * 50 * 2
#define H1_DIM     1000
#define H2_DIM     50
#define OUT_DIM    13
#define N_HEADS    22
#define COMP       50

__device__ __constant__ int d_LOC[23] = {
    0, 2490, 4912, 6895, 8797, 10612, 12320, 13913, 15364, 16748, 18086,
    19437, 20770, 21914, 22984, 24004, 24907, 25740, 26544, 27130, 27774,
    28241, 28749};

// ---------------- scratch (no allocations allowed) ----------------
__device__ float g_combined[BATCH * INPUT_DIM];   // 18 MB
__device__ float g_z[BATCH * INPUT_DIM];          // 18 MB
__device__ float g_h1[BATCH * H1_DIM];            // 8.2 MB
__device__ float g_w2t[H1_DIM * H2_DIM];          // 0.2 MB

// =====================================================================
// Kernel 1: heads.  For segment `seg`, rows r = b*2 + c (4096 rows):
//   acc[r][o] = sum_{l<L} x[r, a+l] * head_w[o, a+l]
//   combined[b, seg*100 + c*50 + o] = acc + head_b[seg, o]
// Tiled 128 rows x 64 cols (cols 50..63 padded/discarded), K-chunks of 32.
// =====================================================================
__global__ __launch_bounds__(256) void k_heads(
    const float* __restrict__ x, const float* __restrict__ hw,
    const float* __restrict__ hb, float* __restrict__ out) {
    const int seg = blockIdx.y;
    const int r0  = blockIdx.x * 128;
    const int a   = d_LOC[seg];
    const int L   = d_LOC[seg + 1] - a;

    __shared__ float As[128][33];  // [row][k]
    __shared__ float Bs[32][65];   // [k][o]

    const int tid = threadIdx.x;
    const int kk  = tid & 31;      // loader: k within chunk
    const int rr  = tid >> 5;      // loader: row/col sub-index (0..7)
    const int rg  = tid & 31;      // compute: row group (rows rg + 32*j)
    const int cg  = tid >> 5;      // compute: col group (cols cg*8 + q)

    float acc[4][8];
#pragma unroll
    for (int j = 0; j < 4; j++)
#pragma unroll
        for (int q = 0; q < 8; q++) acc[j][q] = 0.f;

    for (int k0 = 0; k0 < L; k0 += 32) {
        const bool kin = (k0 + kk) < L;
        // load A tile: 128 rows x 32 k, coalesced along k
#pragma unroll
        for (int p = 0; p < 16; p++) {
            const int r = rr + p * 8;
            As[r][kk] = kin ? x[(size_t)(r0 + r) * TOTAL_BINS + a + k0 + kk] : 0.f;
        }
        // load B tile: Bs[k][o] from head_w[o, a+k]; pad o>=50 with 0
#pragma unroll
        for (int p = 0; p < 8; p++) {
            const int o = rr + p * 8;
            Bs[kk][o] = (kin && o < COMP)
                            ? hw[(size_t)o * TOTAL_BINS + a + k0 + kk]
                            : 0.f;
        }
        __syncthreads();
#pragma unroll
        for (int t = 0; t < 32; t++) {
            float av[4], bv[8];
#pragma unroll
            for (int j = 0; j < 4; j++) av[j] = As[rg + 32 * j][t];
#pragma unroll
            for (int q = 0; q < 8; q++) bv[q] = Bs[t][cg * 8 + q];
#pragma unroll
            for (int j = 0; j < 4; j++)
#pragma unroll
                for (int q = 0; q < 8; q++) acc[j][q] += av[j] * bv[q];
        }
        __syncthreads();
    }

#pragma unroll
    for (int j = 0; j < 4; j++) {
        const int r = r0 + rg + 32 * j;
        const int b = r >> 1, c = r & 1;
        float* orow = out + (size_t)b * INPUT_DIM + seg * 100 + c * 50;
#pragma unroll
        for (int q = 0; q < 8; q++) {
            const int o = cg * 8 + q;
            if (o < COMP) orow[o] = acc[j][q] + hb[seg * COMP + o];
        }
    }
}

// =====================================================================
// Generic GEMM: C[M,N] = A[M,K] @ W[N,K]^T + bias, optional leaky-relu.
// Tile 128x64, K-chunk 32, 4x8 per-thread microtile.
// =====================================================================
template <bool LEAKY>
__global__ __launch_bounds__(256) void k_gemm(
    const float* __restrict__ A, const float* __restrict__ W,
    const float* __restrict__ bias, float* __restrict__ C,
    int M, int N, int K) {
    __shared__ float As[128][33];
    __shared__ float Ws[64][33];

    const int m0 = blockIdx.x * 128;
    const int n0 = blockIdx.y * 64;
    const int tid = threadIdx.x;
    const int kk = tid & 31, rr = tid >> 5;
    const int rg = tid & 31, cg = tid >> 5;

    float acc[4][8];
#pragma unroll
    for (int j = 0; j < 4; j++)
#pragma unroll
        for (int q = 0; q < 8; q++) acc[j][q] = 0.f;

    for (int k0 = 0; k0 < K; k0 += 32) {
        const bool kin = (k0 + kk) < K;
#pragma unroll
        for (int p = 0; p < 16; p++) {
            const int r = rr + p * 8;
            As[r][kk] = kin ? A[(size_t)(m0 + r) * K + k0 + kk] : 0.f;
        }
#pragma unroll
        for (int p = 0; p < 8; p++) {
            const int n = rr + p * 8;
            Ws[n][kk] = (kin && (n0 + n) < N)
                            ? W[(size_t)(n0 + n) * K + k0 + kk]
                            : 0.f;
        }
        __syncthreads();
#pragma unroll
        for (int t = 0; t < 32; t++) {
            float av[4], bv[8];
#pragma unroll
            for (int j = 0; j < 4; j++) av[j] = As[rg + 32 * j][t];
#pragma unroll
            for (int q = 0; q < 8; q++) bv[q] = Ws[cg * 8 + q][t];
#pragma unroll
            for (int j = 0; j < 4; j++)
#pragma unroll
                for (int q = 0; q < 8; q++) acc[j][q] += av[j] * bv[q];
        }
        __syncthreads();
    }

#pragma unroll
    for (int j = 0; j < 4; j++) {
        const int m = m0 + rg + 32 * j;
#pragma unroll
        for (int q = 0; q < 8; q++) {
            const int n = n0 + cg * 8 + q;
            if (n < N) {
                float v = acc[j][q] + bias[n];
                if (LEAKY) v = v > 0.f ? v : 0.01f * v;
                C[(size_t)m * N + n] = v;
            }
        }
    }
}

// transpose w2 (50 x 1000) -> w2t (1000 x 50) for coalesced tail reads
__global__ void k_transpose_w2(const float* __restrict__ w2,
                               float* __restrict__ w2t) {
    int idx = blockIdx.x * 256 + threadIdx.x;
    if (idx < H2_DIM * H1_DIM) {
        int n = idx / H1_DIM, k = idx % H1_DIM;
        w2t[k * H2_DIM + n] = w2[idx];
    }
}

// =====================================================================
// Tail: fused h2 = leaky(h1 @ w2^T + b2); out = h2 @ w3^T + b3.
// One block (128 threads) per batch row.
// =====================================================================
__global__ __launch_bounds__(128) void k_tail(
    const float* __restrict__ h1, const float* __restrict__ w2t,
    const float* __restrict__ b2, const float* __restrict__ w3,
    const float* __restrict__ b3, float* __restrict__ out) {
    const int m = blockIdx.x;
    __shared__ float s[H1_DIM];
    __shared__ float s2[H2_DIM];
    const int tid = threadIdx.x;

    for (int i = tid; i < H1_DIM; i += 128) s[i] = h1[(size_t)m * H1_DIM + i];
    __syncthreads();

    if (tid < H2_DIM) {
        float acc = b2[tid];
#pragma unroll 4
        for (int k = 0; k < H1_DIM; k++) acc += s[k] * w2t[k * H2_DIM + tid];
        s2[tid] = acc > 0.f ? acc : 0.01f * acc;
    }
    __syncthreads();

    if (tid < OUT_DIM) {
        float acc = b3[tid];
#pragma unroll
        for (int k = 0; k < H2_DIM; k++) acc += s2[k] * w3[tid * H2_DIM + k];
        out[(size_t)m * OUT_DIM + tid] = acc;
    }
}

// =====================================================================
extern "C" void kernel_launch(void* const* d_in, const int* in_sizes, int n_in,
                              void* d_out, int out_size) {
    const float* x      = (const float*)d_in[0];
    const float* head_w = (const float*)d_in[1];
    const float* head_b = (const float*)d_in[2];
    const float* conc_w = (const float*)d_in[3];
    const float* conc_b = (const float*)d_in[4];
    const float* w1     = (const float*)d_in[5];
    const float* b1     = (const float*)d_in[6];
    const float* w2     = (const float*)d_in[7];
    const float* b2     = (const float*)d_in[8];
    const float* w3     = (const float*)d_in[9];
    const float* b3     = (const float*)d_in[10];
    float* out = (float*)d_out;

    float *combined, *z, *h1v, *w2t;
    cudaGetSymbolAddress((void**)&combined, g_combined);
    cudaGetSymbolAddress((void**)&z, g_z);
    cudaGetSymbolAddress((void**)&h1v, g_h1);
    cudaGetSymbolAddress((void**)&w2t, g_w2t);

    // Stage 1: 22 block-diagonal head GEMMs -> combined (2048 x 2200)
    k_heads<<<dim3(ROWS / 128, N_HEADS), 256>>>(x, head_w, head_b, combined);

    // Stage 2: z = combined @ conc_w^T + conc_b   (2048 x 2200)
    k_gemm<false><<<dim3(BATCH / 128, (INPUT_DIM + 63) / 64), 256>>>(
        combined, conc_w, conc_b, z, BATCH, INPUT_DIM, INPUT_DIM);

    // Stage 3: h1 = leaky(z @ w1^T + b1)          (2048 x 1000)
    k_gemm<true><<<dim3(BATCH / 128, (H1_DIM + 63) / 64), 256>>>(
        z, w1, b1, h1v, BATCH, H1_DIM, INPUT_DIM);

    // Stage 4+5 fused tail
    k_transpose_w2<<<(H1_DIM * H2_DIM + 255) / 256, 256>>>(w2, w2t);
    k_tail<<<BATCH, 128>>>(h1v, w2t, b2, w3, b3, out);
}

// round 7
// speedup vs baseline: 1.8006x; 1.8006x over previous
#include <cuda_runtime.h>
#include <cuda_bf16.h>
#include <cstdint>

// ---------------- problem constants ----------------
#define TOTAL_BINS 28749
#define BATCH      2048
#define ROWS       4096      // BATCH * 2 channels
#define INPUT_DIM  2200      // 22 * 50 * 2
#define H1_DIM     1000
#define H2_DIM     50
#define OUT_DIM    13
#define N_HEADS    22
#define COMP       50

__device__ __constant__ int d_LOC[23] = {
    0, 2490, 4912, 6895, 8797, 10612, 12320, 13913, 15364, 16748, 18086,
    19437, 20770, 21914, 22984, 24004, 24907, 25740, 26544, 27130, 27774,
    28241, 28749};

// ---------------- scratch (no allocations allowed) ----------------
__device__ float g_combined[BATCH * INPUT_DIM];
__device__ float g_z[BATCH * INPUT_DIM];
__device__ float g_h1[BATCH * H1_DIM];
__device__ float g_w2t[H1_DIM * H2_DIM];

// ---------------- smem layout (dynamic), bf16 tiles, pitch 72 bf16 ----
#define PITCH_B   144        // 72 bf16 * 2 bytes
#define OFF_AH    0          // 128 x 72 bf16 = 18432 B
#define OFF_AL    18432
#define OFF_WH    36864      // 64 x 72 bf16 = 9216 B
#define OFF_WL    46080
#define SMEM_TOTAL 55296

__device__ __forceinline__ uint32_t su32(const void* p) {
    uint32_t a;
    asm("{ .reg .u64 t; cvta.to.shared.u64 t, %1; cvt.u32.u64 %0, t; }"
        : "=r"(a) : "l"(p));
    return a;
}

#define LDSM4(r0, r1, r2, r3, addr)                                          \
    asm volatile(                                                            \
        "ldmatrix.sync.aligned.m8n8.x4.shared.b16 {%0,%1,%2,%3}, [%4];"      \
        : "=r"(r0), "=r"(r1), "=r"(r2), "=r"(r3) : "r"(addr))

__device__ __forceinline__ void mma_bf16(float* d, const uint32_t* a,
                                         uint32_t b0, uint32_t b1) {
    asm volatile(
        "mma.sync.aligned.m16n8k16.row.col.f32.bf16.bf16.f32 "
        "{%0,%1,%2,%3}, {%4,%5,%6,%7}, {%8,%9}, {%0,%1,%2,%3};"
        : "+f"(d[0]), "+f"(d[1]), "+f"(d[2]), "+f"(d[3])
        : "r"(a[0]), "r"(a[1]), "r"(a[2]), "r"(a[3]), "r"(b0), "r"(b1));
}

__device__ __forceinline__ void split_pack(float v0, float v1, uint32_t& hp,
                                           uint32_t& lp) {
    const __nv_bfloat16 h0 = __float2bfloat16(v0);
    const __nv_bfloat16 h1 = __float2bfloat16(v1);
    const __nv_bfloat16 l0 = __float2bfloat16(v0 - __bfloat162float(h0));
    const __nv_bfloat16 l1 = __float2bfloat16(v1 - __bfloat162float(h1));
    hp = ((uint32_t)__bfloat16_as_ushort(h1) << 16) | __bfloat16_as_ushort(h0);
    lp = ((uint32_t)__bfloat16_as_ushort(l1) << 16) | __bfloat16_as_ushort(l0);
}

// =====================================================================
// Tensor-core GEMM via mma.sync, bf16 hi/lo split (3 products):
//   C[M,N] = A[M,K] @ W[N,K]^T + bias  (opt leaky)
// EPI: 0 = plain, 1 = leaky, 2 = heads (segmented K, scatter output)
// Block: 256 thr (8 warps, 4x2), tile M=128 x N=64, K-chunk 64.
// =====================================================================
template <int EPI>
__global__ __launch_bounds__(256) void k_mma(
    const float* __restrict__ Ain, int lda, const float* __restrict__ Win,
    int ldw, const float* __restrict__ bias_in, float* __restrict__ C,
    int ldc, int Nin, int Kin) {
    extern __shared__ __align__(16) char smem[];
    const uint32_t sb = su32(smem);
    const int tid = threadIdx.x;
    const int lane = tid & 31, wid = tid >> 5;
    const int wm = wid & 3, wn = wid >> 2;   // warp 32-row group, 32-col group
    const int m0 = blockIdx.x * 128;

    const float* A = Ain;
    const float* W = Win;
    const float* bias = bias_in;
    int N = Nin, K = Kin, n0 = 0, seg = 0;
    if (EPI == 2) {
        seg = blockIdx.y;
        const int a = d_LOC[seg];
        K = d_LOC[seg + 1] - a;
        A = Ain + a;
        W = Win + a;
        bias = bias_in + seg * COMP;
        N = COMP;
    } else {
        n0 = blockIdx.y * 64;
    }
    const int nv = (N - n0 < 64) ? (N - n0) : 64;  // valid cols in this tile

    float acc[2][4][4];
#pragma unroll
    for (int mt = 0; mt < 2; mt++)
#pragma unroll
        for (int nt = 0; nt < 4; nt++)
#pragma unroll
            for (int q = 0; q < 4; q++) acc[mt][nt][q] = 0.f;

    // per-thread ldmatrix smem addresses (byte offsets fixed across chunks)
    // A frag (m8n8.x4 over 16x16): lanes 0-15 -> rows 0..15, lanes 16-31 -> +8 cols
    const uint32_t a_row = (uint32_t)(wm * 32 + (lane & 15));
    const uint32_t a_cb  = (uint32_t)((lane >> 4) << 4);      // +16 B for k+8
    // W frag (x4 over two 8-row n-tiles x 16 k)
    const uint32_t w_row = (uint32_t)(wn * 32 + ((lane >> 4) << 3) + (lane & 7));
    const uint32_t w_cb  = (uint32_t)((lane & 8) * 2);        // +16 B for k+8

    const int nch = (K + 63) >> 6;
    for (int ch = 0; ch < nch; ch++) {
        const int k0 = ch << 6;
        if (ch) __syncthreads();   // protect smem from previous iteration's reads

        // ---- load + convert A tile: 128 rows x 32 bf16x2 pairs ----
#pragma unroll
        for (int i = 0; i < 16; i++) {
            const int idx = i * 256 + tid;
            const int row = idx >> 5, kp = idx & 31;
            const int k = k0 + kp * 2;
            const float* ap = A + (size_t)(m0 + row) * lda + k;
            const float v0 = (k < K) ? ap[0] : 0.f;
            const float v1 = (k + 1 < K) ? ap[1] : 0.f;
            uint32_t hp, lp;
            split_pack(v0, v1, hp, lp);
            const uint32_t o = row * PITCH_B + kp * 4;
            *(uint32_t*)(smem + OFF_AH + o) = hp;
            *(uint32_t*)(smem + OFF_AL + o) = lp;
        }
        // ---- load + convert W tile: 64 rows x 32 pairs ----
#pragma unroll
        for (int i = 0; i < 8; i++) {
            const int idx = i * 256 + tid;
            const int row = idx >> 5, kp = idx & 31;
            const int k = k0 + kp * 2;
            const bool rv = row < nv;
            const float* wp = W + (size_t)(n0 + row) * ldw + k;
            const float v0 = (rv && k < K) ? wp[0] : 0.f;
            const float v1 = (rv && k + 1 < K) ? wp[1] : 0.f;
            uint32_t hp, lp;
            split_pack(v0, v1, hp, lp);
            const uint32_t o = row * PITCH_B + kp * 4;
            *(uint32_t*)(smem + OFF_WH + o) = hp;
            *(uint32_t*)(smem + OFF_WL + o) = lp;
        }
        __syncthreads();

#pragma unroll
        for (int ks = 0; ks < 4; ks++) {
            const uint32_t acb = ks * 32 + a_cb;
            const uint32_t wcb = ks * 32 + w_cb;
            uint32_t ah[2][4], al[2][4], wh[4][2], wl[4][2];
#pragma unroll
            for (int mt = 0; mt < 2; mt++) {
                const uint32_t ro = (a_row + mt * 16) * PITCH_B + acb;
                LDSM4(ah[mt][0], ah[mt][1], ah[mt][2], ah[mt][3],
                      sb + OFF_AH + ro);
                LDSM4(al[mt][0], al[mt][1], al[mt][2], al[mt][3],
                      sb + OFF_AL + ro);
            }
#pragma unroll
            for (int p = 0; p < 2; p++) {
                const uint32_t ro = (w_row + p * 16) * PITCH_B + wcb;
                LDSM4(wh[2 * p][0], wh[2 * p][1], wh[2 * p + 1][0],
                      wh[2 * p + 1][1], sb + OFF_WH + ro);
                LDSM4(wl[2 * p][0], wl[2 * p][1], wl[2 * p + 1][0],
                      wl[2 * p + 1][1], sb + OFF_WL + ro);
            }
#pragma unroll
            for (int mt = 0; mt < 2; mt++)
#pragma unroll
                for (int nt = 0; nt < 4; nt++) {
                    mma_bf16(acc[mt][nt], ah[mt], wh[nt][0], wh[nt][1]);
                    mma_bf16(acc[mt][nt], ah[mt], wl[nt][0], wl[nt][1]);
                    mma_bf16(acc[mt][nt], al[mt], wh[nt][0], wh[nt][1]);
                }
        }
    }

    // ---- epilogue: registers -> global (float2 pairs, cols adjacent) ----
#pragma unroll
    for (int mt = 0; mt < 2; mt++) {
        const int rowl = wm * 32 + mt * 16 + (lane >> 2);
#pragma unroll
        for (int nt = 0; nt < 4; nt++) {
            const int col = wn * 32 + nt * 8 + 2 * (lane & 3);
            if (col >= nv) continue;
            if (EPI == 2) {
                const float b0 = bias[col], b1 = bias[col + 1];
#pragma unroll
                for (int h = 0; h < 2; h++) {
                    const int r = m0 + rowl + h * 8;
                    const int b = r >> 1, c = r & 1;
                    float2 v = {acc[mt][nt][2 * h] + b0,
                                acc[mt][nt][2 * h + 1] + b1};
                    *(float2*)(C + (size_t)b * INPUT_DIM + seg * 100 +
                               c * COMP + col) = v;
                }
            } else {
                const int n = n0 + col;
                const float b0 = bias[n], b1 = bias[n + 1];
#pragma unroll
                for (int h = 0; h < 2; h++) {
                    float v0 = acc[mt][nt][2 * h] + b0;
                    float v1 = acc[mt][nt][2 * h + 1] + b1;
                    if (EPI == 1) {
                        v0 = v0 > 0.f ? v0 : 0.01f * v0;
                        v1 = v1 > 0.f ? v1 : 0.01f * v1;
                    }
                    float2 v = {v0, v1};
                    *(float2*)(C + (size_t)(m0 + rowl + h * 8) * ldc + n) = v;
                }
            }
        }
    }
}

// transpose w2 (50 x 1000) -> w2t (1000 x 50)
__global__ void k_transpose_w2(const float* __restrict__ w2,
                               float* __restrict__ w2t) {
    int idx = blockIdx.x * 256 + threadIdx.x;
    if (idx < H2_DIM * H1_DIM) {
        int n = idx / H1_DIM, k = idx % H1_DIM;
        w2t[k * H2_DIM + n] = w2[idx];
    }
}

// fused tail: h2 = leaky(h1 @ w2^T + b2); out = h2 @ w3^T + b3
__global__ __launch_bounds__(128) void k_tail(
    const float* __restrict__ h1, const float* __restrict__ w2t,
    const float* __restrict__ b2, const float* __restrict__ w3,
    const float* __restrict__ b3, float* __restrict__ out) {
    const int m = blockIdx.x;
    __shared__ float s[H1_DIM];
    __shared__ float s2[H2_DIM];
    const int tid = threadIdx.x;

    for (int i = tid; i < H1_DIM; i += 128) s[i] = h1[(size_t)m * H1_DIM + i];
    __syncthreads();

    if (tid < H2_DIM) {
        float acc = b2[tid];
#pragma unroll 4
        for (int k = 0; k < H1_DIM; k++) acc += s[k] * w2t[k * H2_DIM + tid];
        s2[tid] = acc > 0.f ? acc : 0.01f * acc;
    }
    __syncthreads();

    if (tid < OUT_DIM) {
        float acc = b3[tid];
#pragma unroll
        for (int k = 0; k < H2_DIM; k++) acc += s2[k] * w3[tid * H2_DIM + k];
        out[(size_t)m * OUT_DIM + tid] = acc;
    }
}

// =====================================================================
extern "C" void kernel_launch(void* const* d_in, const int* in_sizes, int n_in,
                              void* d_out, int out_size) {
    const float* x      = (const float*)d_in[0];
    const float* head_w = (const float*)d_in[1];
    const float* head_b = (const float*)d_in[2];
    const float* conc_w = (const float*)d_in[3];
    const float* conc_b = (const float*)d_in[4];
    const float* w1     = (const float*)d_in[5];
    const float* b1     = (const float*)d_in[6];
    const float* w2     = (const float*)d_in[7];
    const float* b2     = (const float*)d_in[8];
    const float* w3     = (const float*)d_in[9];
    const float* b3     = (const float*)d_in[10];
    float* out = (float*)d_out;

    float *combined, *z, *h1v, *w2t;
    cudaGetSymbolAddress((void**)&combined, g_combined);
    cudaGetSymbolAddress((void**)&z, g_z);
    cudaGetSymbolAddress((void**)&h1v, g_h1);
    cudaGetSymbolAddress((void**)&w2t, g_w2t);

    cudaFuncSetAttribute(k_mma<0>, cudaFuncAttributeMaxDynamicSharedMemorySize,
                         SMEM_TOTAL);
    cudaFuncSetAttribute(k_mma<1>, cudaFuncAttributeMaxDynamicSharedMemorySize,
                         SMEM_TOTAL);
    cudaFuncSetAttribute(k_mma<2>, cudaFuncAttributeMaxDynamicSharedMemorySize,
                         SMEM_TOTAL);

    // Stage 1: 22 block-diagonal head GEMMs -> combined (2048 x 2200)
    k_mma<2><<<dim3(ROWS / 128, N_HEADS), 256, SMEM_TOTAL>>>(
        x, TOTAL_BINS, head_w, TOTAL_BINS, head_b, combined, 0, 0, 0);

    // Stage 2: z = combined @ conc_w^T + conc_b (2048 x 2200)
    k_mma<0><<<dim3(BATCH / 128, (INPUT_DIM + 63) / 64), 256, SMEM_TOTAL>>>(
        combined, INPUT_DIM, conc_w, INPUT_DIM, conc_b, z, INPUT_DIM,
        INPUT_DIM, INPUT_DIM);

    // Stage 3: h1 = leaky(z @ w1^T + b1) (2048 x 1000)
    k_mma<1><<<dim3(BATCH / 128, (H1_DIM + 63) / 64), 256, SMEM_TOTAL>>>(
        z, INPUT_DIM, w1, INPUT_DIM, b1, h1v, H1_DIM, H1_DIM, INPUT_DIM);

    // Stage 4+5 fused tail
    k_transpose_w2<<<(H1_DIM * H2_DIM + 255) / 256, 256>>>(w2, w2t);
    k_tail<<<BATCH, 128>>>(h1v, w2t, b2, w3, b3, out);
}